// round 7
// baseline (speedup 1.0000x reference)
#include <cuda_runtime.h>
#include <cstdint>

#define B 4
#define N 1024
#define F 256
#define W 32            // 32 x u32 words per 1024-bit row
#define FULL 0xFFFFFFFFu

#define PACK_BLKS 512   // 512 blocks * 8 warps = 4096 rows
#define TOTAL_BLKS 2048 // extra 1536 blocks do the zero-fill
#define MAXK 344        // smem row-cache capacity in a_kernel (guarded fallback)
#define MAXL 128        // neighbor-list capacity in xp_kernel
#define ECAP 40         // sparse exc-list capacity per row (fallback if exceeded)

// ---------------- scratch (device globals; no allocations allowed) ----------
__device__ unsigned       g_bitsA  [B][N][W];    // adj rows (node space)
__device__ unsigned       g_bits1  [B][N][W];    // (adj+I) rows (node space)
__device__ unsigned       g_excRd  [B][N][W];    // dense exc rows, rank space (fallback)
__device__ unsigned       g_incRd  [B][N][W];    // dense inc rows, rank space
__device__ unsigned short g_excList[B][N][ECAP]; // sparse exc (rank entries)
__device__ unsigned short g_excCnt [B][N];       // count or 0xFFFF sentinel
__device__ int            g_rank   [B][N];
__device__ int            g_inv    [B][N];
__device__ int            g_perm   [B][N];
__device__ int            g_K      [B];

// Output layout (float32, concatenated):
#define OFF_X   0
#define OFF_P   (B*N*F)
#define OFF_A   (B*N*F + B*N*3)
#define OFF_M   (B*N*F + B*N*3 + B*N*N)
#define NZERO4  ((B*N*F + B*N*3 + B*N*N) / 4)

// ---------------- K0: pack adj rows into bitmasks + zero-fill outputs -------
__global__ void pack_zero_kernel(const float* __restrict__ adj, float* __restrict__ out) {
    if (blockIdx.x >= PACK_BLKS) {
        int zb = blockIdx.x - PACK_BLKS;
        float4 z = make_float4(0.f, 0.f, 0.f, 0.f);
        float4* o = (float4*)out;
        for (int i = zb * blockDim.x + threadIdx.x; i < NZERO4;
             i += (TOTAL_BLKS - PACK_BLKS) * blockDim.x)
            o[i] = z;
        return;
    }
    int warp = (blockIdx.x * blockDim.x + threadIdx.x) >> 5;   // 0..4095
    int lane = threadIdx.x & 31;
    int b = warp >> 10, i = warp & (N - 1);
    const float4* r4 = (const float4*)(adj + ((size_t)b * N + i) * N) + lane * 8;
    unsigned w = 0;
    #pragma unroll
    for (int j = 0; j < 8; ++j) {
        float4 v = r4[j];
        w |= (v.x != 0.f ? 1u : 0u) << (4 * j)
           | (v.y != 0.f ? 1u : 0u) << (4 * j + 1)
           | (v.z != 0.f ? 1u : 0u) << (4 * j + 2)
           | (v.w != 0.f ? 1u : 0u) << (4 * j + 3);
    }
    g_bitsA[b][i][lane] = w;
    unsigned m1 = w | ((lane == (i >> 5)) ? (1u << (i & 31)) : 0u);
    g_bits1[b][i][lane] = m1;
}

// ---------------- K1: stable rank of each node by order value ---------------
__global__ void rank_kernel(const float* __restrict__ order) {
    int b = blockIdx.x >> 3;
    int i = (blockIdx.x & 7) * 128 + threadIdx.x;
    __shared__ float so[N];
    for (int j = threadIdx.x; j < N; j += 128) so[j] = order[b * N + j];
    __syncthreads();
    float oi = so[i];
    int r = 0;
    const float4* s4 = (const float4*)so;
    #pragma unroll 8
    for (int j4 = 0; j4 < N / 4; ++j4) {
        float4 v = s4[j4];
        int j = j4 * 4;
        r += (v.x < oi) || (v.x == oi && (j + 0) < i);
        r += (v.y < oi) || (v.y == oi && (j + 1) < i);
        r += (v.z < oi) || (v.z == oi && (j + 2) < i);
        r += (v.w < oi) || (v.w == oi && (j + 3) < i);
    }
    g_rank[b][i] = r;
    g_inv[b][r] = i;
}

// ---------------- K2: inc rows + permute to RANK space + sparse exc ---------
__global__ void inc_perm_kernel() {
    int warp = (blockIdx.x * blockDim.x + threadIdx.x) >> 5;
    int lane = threadIdx.x & 31;
    int b = warp >> 10, i = warp & (N - 1);
    unsigned exc = g_bits1[b][i][lane];
    unsigned acc = 0;
    #pragma unroll 4
    for (int w = 0; w < W; ++w) {
        unsigned word = __shfl_sync(FULL, exc, w);
        while (word) {
            int bit = __ffs(word) - 1;
            word &= word - 1;
            acc |= g_bitsA[b][w * 32 + bit][lane];
        }
    }
    // column permutation to rank space
    int sj[32];
    const int4* inv4 = (const int4*)&g_inv[b][0];
    #pragma unroll
    for (int q = 0; q < 8; ++q) {
        int4 v = inv4[lane * 8 + q];
        sj[4 * q] = v.x; sj[4 * q + 1] = v.y; sj[4 * q + 2] = v.z; sj[4 * q + 3] = v.w;
    }
    unsigned excw = 0, incw = 0;
    #pragma unroll
    for (int t = 0; t < 32; ++t) {
        int j = sj[t];
        unsigned ew = __shfl_sync(FULL, exc, j >> 5);
        unsigned iw = __shfl_sync(FULL, acc, j >> 5);
        excw |= ((ew >> (j & 31)) & 1u) << t;
        incw |= ((iw >> (j & 31)) & 1u) << t;
    }
    int r = g_rank[b][i];
    g_excRd[b][r][lane] = excw;
    g_incRd[b][r][lane] = incw;

    // sparse exc list (rank entries), warp-compacted
    int c = __popc(excw);
    int v = c;
    #pragma unroll
    for (int o = 1; o < 32; o <<= 1) {
        int t = __shfl_up_sync(FULL, v, o);
        if (lane >= o) v += t;
    }
    int tot = __shfl_sync(FULL, v, 31);
    if (lane == 0) g_excCnt[b][r] = (tot <= ECAP) ? (unsigned short)tot : (unsigned short)0xFFFF;
    if (tot <= ECAP) {
        int p = v - c;
        unsigned m = excw;
        while (m) {
            int t = __ffs(m) - 1;
            m &= m - 1;
            g_excList[b][r][p++] = (unsigned short)(lane * 32 + t);
        }
    }
}

// ---------------- K3: serial greedy selection, all-SMEM (1 block/batch) -----
// dynamic smem layout:
//   [0)                 unsigned sInc[N*W]          131072 B
//   [131072)            unsigned short sList[N*ECAP] 81920 B
//   [212992)            unsigned short sCnt[N]        2048 B
//   [215040)            int sinv[N]                   4096 B
#define SMEM_SEL_BYTES (131072 + 81920 + 2048 + 4096)

__global__ void select_kernel(float* __restrict__ out_mask) {
    extern __shared__ char sm[];
    unsigned*       sInc  = (unsigned*)sm;
    unsigned short* sList = (unsigned short*)(sm + 131072);
    unsigned short* sCnt  = (unsigned short*)(sm + 212992);
    int*            sinv  = (int*)(sm + 215040);
    __shared__ unsigned snode[W];

    int b = blockIdx.x;
    int tid = threadIdx.x;
    // cooperative staging from L2 (256 threads)
    {
        const uint4* src = (const uint4*)&g_incRd[b][0][0];
        uint4* dst = (uint4*)sInc;
        #pragma unroll
        for (int i = tid; i < (N * W) / 4; i += 256) dst[i] = src[i];
        const uint4* ls = (const uint4*)&g_excList[b][0][0];
        uint4* ld = (uint4*)sList;
        #pragma unroll
        for (int i = tid; i < (N * ECAP * 2) / 16; i += 256) ld[i] = ls[i];
        const uint4* cs = (const uint4*)&g_excCnt[b][0];
        uint4* cd = (uint4*)sCnt;
        for (int i = tid; i < (N * 2) / 16; i += 256) cd[i] = cs[i];
        const int4* is = (const int4*)&g_inv[b][0];
        int4* id = (int4*)sinv;
        for (int i = tid; i < N / 4; i += 256) id[i] = is[i];
        if (tid < W) snode[tid] = 0;
    }
    __syncthreads();
    if (tid >= 32) return;                    // warp 0 runs the serial loop
    int lane = tid;

    unsigned av = FULL;                       // node_mask all-true
    unsigned sel = 0;                         // rank-space selected set
    unsigned fr = (lane == 0) ? 1u : 0u;      // initial frontier = rank 0
    int r = 0;

    int guard = 0;
    while (guard++ < 2 * N) {
        if (lane == (r >> 5)) sel |= 1u << (r & 31);
        int cnt = sCnt[r];
        if (cnt <= ECAP) {                    // sparse exc (self bit included)
            const unsigned short* lst = sList + r * ECAP;
            int j = 0;
            for (; j + 4 <= cnt; j += 4) {
                int e0 = lst[j], e1 = lst[j+1], e2 = lst[j+2], e3 = lst[j+3];
                unsigned m = 0;
                if ((e0 >> 5) == lane) m |= 1u << (e0 & 31);
                if ((e1 >> 5) == lane) m |= 1u << (e1 & 31);
                if ((e2 >> 5) == lane) m |= 1u << (e2 & 31);
                if ((e3 >> 5) == lane) m |= 1u << (e3 & 31);
                av &= ~m;
            }
            for (; j < cnt; ++j) {
                int e = lst[j];
                if ((e >> 5) == lane) av &= ~(1u << (e & 31));
            }
        } else {
            av &= ~g_excRd[b][r][lane];       // rare fallback
        }
        fr = (fr | sInc[r * 32 + lane]) & av;
        unsigned bal = __ballot_sync(FULL, fr != 0u);
        if (!bal) {                           // frontier died -> restart on av
            fr = av;
            bal = __ballot_sync(FULL, av != 0u);
            if (!bal) break;
        }
        int lead = __ffs(bal) - 1;
        unsigned wrd = __shfl_sync(FULL, fr, lead);
        r = lead * 32 + (__ffs(wrd) - 1);     // min rank in frontier
    }

    // convert rank-space sel to node space
    unsigned m = sel;
    while (m) {
        int t = __ffs(m) - 1;
        m &= m - 1;
        int node = sinv[lane * 32 + t];
        atomicOr(&snode[node >> 5], 1u << (node & 31));
    }
    __syncwarp();
    unsigned selN = snode[lane];

    // stable top_k permutation: selected ascending, then unselected ascending
    int cnt = __popc(selN);
    int v = cnt;
    #pragma unroll
    for (int o = 1; o < 32; o <<= 1) {
        int n2 = __shfl_up_sync(FULL, v, o);
        if (lane >= o) v += n2;
    }
    int K = __shfl_sync(FULL, v, 31);
    int selpos = v - cnt;
    int unspos = K + (lane * 32 - selpos);
    #pragma unroll
    for (int i = 0; i < 32; ++i) {
        int node = lane * 32 + i;
        if ((selN >> i) & 1u) g_perm[b][selpos++] = node;
        else                  g_perm[b][unspos++] = node;
    }
    if (lane == 0) g_K[b] = K;
    #pragma unroll
    for (int w = 0; w < W; ++w) {
        int j = w * 32 + lane;
        out_mask[b * N + j] = (j < K) ? 1.0f : 0.0f;
    }
}

// ---------------- K4: pooled features x_p and pos_p (live rows only) --------
__global__ void xp_kernel(const float* __restrict__ x, const float* __restrict__ pos,
                          float* __restrict__ out_x, float* __restrict__ out_pos) {
    int b = blockIdx.y, k = blockIdx.x;
    if (k >= g_K[b]) return;                   // padding already zero-filled
    int f = threadIdx.x;                       // 256 threads == F
    __shared__ int spk, snn;
    __shared__ int list[MAXL];
    if (f == 0) spk = g_perm[b][k];
    __syncthreads();
    if (f < 32) {
        unsigned wd = g_bits1[b][spk][f];
        int c = __popc(wd);
        int v = c;
        #pragma unroll
        for (int o = 1; o < 32; o <<= 1) {
            int t = __shfl_up_sync(FULL, v, o);
            if (f >= o) v += t;
        }
        int p = v - c;
        while (wd) {
            int bt = __ffs(wd) - 1;
            wd &= wd - 1;
            list[p++] = f * 32 + bt;
        }
        if (f == 31) snn = v;
    }
    __syncthreads();
    int nn = snn;

    float acc = 0.0f;
    #pragma unroll 4
    for (int i = 0; i < nn; ++i)
        acc += x[((size_t)b * N + list[i]) * F + f];
    out_x[((size_t)b * N + k) * F + f] = acc;

    if (f < 3) {
        float p = 0.0f;
        for (int i = 0; i < nn; ++i)
            p += pos[((size_t)b * N + list[i]) * 3 + f];
        out_pos[((size_t)b * N + k) * 3 + f] = p / (float)nn;
    }
}

// ---------------- K5: coarsened adjacency, one block per batch --------------
__global__ void a_kernel(float* __restrict__ out_a) {
    int b = blockIdx.x;
    int K = g_K[b];
    __shared__ unsigned srows[MAXK][33];
    __shared__ int sperm[MAXK];
    int KC = K < MAXK ? K : MAXK;
    for (int j = threadIdx.x; j < KC; j += blockDim.x) sperm[j] = g_perm[b][j];
    __syncthreads();
    for (int t = threadIdx.x; t < KC * W; t += blockDim.x) {
        int j = t >> 5, w = t & 31;
        srows[j][w] = g_bitsA[b][sperm[j]][w];
    }
    __syncthreads();
    for (int idx = threadIdx.x; idx < K * K; idx += blockDim.x) {
        int i = idx / K, j = idx - i * K;
        int pi = (i < KC) ? sperm[i] : g_perm[b][i];
        const unsigned* ri = (i < KC) ? &srows[i][0] : &g_bitsA[b][pi][0];
        const unsigned* rj;
        if (j < KC) rj = &srows[j][0];
        else        rj = &g_bitsA[b][g_perm[b][j]][0];
        int s = 0;
        #pragma unroll
        for (int w = 0; w < W; ++w) s += __popc(ri[w] & rj[w]);
        s += (rj[pi >> 5] >> (pi & 31)) & 1;   // diagonal self-term of (A+I)@A
        out_a[((size_t)b * N + i) * N + j] = (float)s;
    }
}

// ---------------- launch ----------------------------------------------------
extern "C" void kernel_launch(void* const* d_in, const int* in_sizes, int n_in,
                              void* d_out, int out_size) {
    const float *x = nullptr, *adj = nullptr, *pos = nullptr, *order = nullptr;
    for (int i = 0; i < n_in; ++i) {
        if      (in_sizes[i] == B * N * N) adj   = (const float*)d_in[i];
        else if (in_sizes[i] == B * N * F) x     = (const float*)d_in[i];
        else if (in_sizes[i] == B * N * 3) pos   = (const float*)d_in[i];
        else if (in_sizes[i] == B * N) { if (!order) order = (const float*)d_in[i]; }
    }
    float* out = (float*)d_out;

    cudaFuncSetAttribute(select_kernel,
                         cudaFuncAttributeMaxDynamicSharedMemorySize, SMEM_SEL_BYTES);

    pack_zero_kernel<<<TOTAL_BLKS, 256>>>(adj, out);
    rank_kernel     <<<B * 8, 128>>>(order);
    inc_perm_kernel <<<(B * N) / 8, 256>>>();
    select_kernel   <<<B, 256, SMEM_SEL_BYTES>>>(out + OFF_M);
    {
        dim3 g(N, B);
        xp_kernel<<<g, F>>>(x, pos, out + OFF_X, out + OFF_P);
    }
    a_kernel<<<B, 1024>>>(out + OFF_A);
}

// round 8
// speedup vs baseline: 1.2545x; 1.2545x over previous
#include <cuda_runtime.h>
#include <cstdint>

#define B 4
#define N 1024
#define F 256
#define W 32            // 32 x u32 words per 1024-bit row
#define FULL 0xFFFFFFFFu

#define PACK_BLKS 512   // 512 blocks * 8 warps = 4096 rows
#define TOTAL_BLKS 2048 // extra 1536 blocks do the zero-fill
#define MAXK 344        // smem row-cache capacity in a_kernel (guarded fallback)
#define MAXL 128        // neighbor-list capacity in xp_kernel
#define ECAP 44         // sparse exc-list capacity per row (dense fallback if exceeded)

// ---------------- scratch (device globals; no allocations allowed) ----------
__device__ unsigned       g_bitsA  [B][N][W];    // adj rows (node space)
__device__ unsigned       g_bits1  [B][N][W];    // (adj+I) rows (node space)
__device__ unsigned       g_excRd  [B][N][W];    // dense exc rows, rank space (fallback)
__device__ unsigned       g_incRd  [B][N][W];    // dense inc rows, rank space
__device__ __align__(16) unsigned short g_excList[B][N][ECAP]; // sparse exc (rank entries, 0xFFFF pad)
__device__ __align__(16) unsigned short g_excCnt [B][N];       // count or 0xFFFF sentinel
__device__ int            g_rank   [B][N];
__device__ int            g_inv    [B][N];
__device__ int            g_perm   [B][N];
__device__ int            g_K      [B];

// Output layout (float32, concatenated):
#define OFF_X   0
#define OFF_P   (B*N*F)
#define OFF_A   (B*N*F + B*N*3)
#define OFF_M   (B*N*F + B*N*3 + B*N*N)
#define NZERO4  ((B*N*F + B*N*3 + B*N*N) / 4)

// ---------------- K0: pack adj rows into bitmasks + zero-fill outputs -------
__global__ void pack_zero_kernel(const float* __restrict__ adj, float* __restrict__ out) {
    if (blockIdx.x >= PACK_BLKS) {
        int zb = blockIdx.x - PACK_BLKS;
        float4 z = make_float4(0.f, 0.f, 0.f, 0.f);
        float4* o = (float4*)out;
        for (int i = zb * blockDim.x + threadIdx.x; i < NZERO4;
             i += (TOTAL_BLKS - PACK_BLKS) * blockDim.x)
            o[i] = z;
        return;
    }
    int warp = (blockIdx.x * blockDim.x + threadIdx.x) >> 5;   // 0..4095
    int lane = threadIdx.x & 31;
    int b = warp >> 10, i = warp & (N - 1);
    const float4* r4 = (const float4*)(adj + ((size_t)b * N + i) * N) + lane * 8;
    unsigned w = 0;
    #pragma unroll
    for (int j = 0; j < 8; ++j) {
        float4 v = r4[j];
        w |= (v.x != 0.f ? 1u : 0u) << (4 * j)
           | (v.y != 0.f ? 1u : 0u) << (4 * j + 1)
           | (v.z != 0.f ? 1u : 0u) << (4 * j + 2)
           | (v.w != 0.f ? 1u : 0u) << (4 * j + 3);
    }
    g_bitsA[b][i][lane] = w;
    unsigned m1 = w | ((lane == (i >> 5)) ? (1u << (i & 31)) : 0u);
    g_bits1[b][i][lane] = m1;
}

// ---------------- K1: stable rank of each node by order value ---------------
__global__ void rank_kernel(const float* __restrict__ order) {
    int b = blockIdx.x >> 3;
    int i = (blockIdx.x & 7) * 128 + threadIdx.x;
    __shared__ float so[N];
    for (int j = threadIdx.x; j < N; j += 128) so[j] = order[b * N + j];
    __syncthreads();
    float oi = so[i];
    int r = 0;
    const float4* s4 = (const float4*)so;
    #pragma unroll 8
    for (int j4 = 0; j4 < N / 4; ++j4) {
        float4 v = s4[j4];
        int j = j4 * 4;
        r += (v.x < oi) || (v.x == oi && (j + 0) < i);
        r += (v.y < oi) || (v.y == oi && (j + 1) < i);
        r += (v.z < oi) || (v.z == oi && (j + 2) < i);
        r += (v.w < oi) || (v.w == oi && (j + 3) < i);
    }
    g_rank[b][i] = r;
    g_inv[b][r] = i;
}

// ---------------- K2: inc rows + permute to RANK space + padded sparse exc --
__global__ void inc_perm_kernel() {
    int warp = (blockIdx.x * blockDim.x + threadIdx.x) >> 5;
    int wInB = (threadIdx.x >> 5);           // 0..7
    int lane = threadIdx.x & 31;
    int b = warp >> 10, i = warp & (N - 1);
    __shared__ unsigned short wst[8][ECAP];

    unsigned exc = g_bits1[b][i][lane];
    unsigned acc = 0;
    #pragma unroll 4
    for (int w = 0; w < W; ++w) {
        unsigned word = __shfl_sync(FULL, exc, w);
        while (word) {
            int bit = __ffs(word) - 1;
            word &= word - 1;
            acc |= g_bitsA[b][w * 32 + bit][lane];
        }
    }
    // column permutation to rank space
    int sj[32];
    const int4* inv4 = (const int4*)&g_inv[b][0];
    #pragma unroll
    for (int q = 0; q < 8; ++q) {
        int4 v = inv4[lane * 8 + q];
        sj[4 * q] = v.x; sj[4 * q + 1] = v.y; sj[4 * q + 2] = v.z; sj[4 * q + 3] = v.w;
    }
    unsigned excw = 0, incw = 0;
    #pragma unroll
    for (int t = 0; t < 32; ++t) {
        int j = sj[t];
        unsigned ew = __shfl_sync(FULL, exc, j >> 5);
        unsigned iw = __shfl_sync(FULL, acc, j >> 5);
        excw |= ((ew >> (j & 31)) & 1u) << t;
        incw |= ((iw >> (j & 31)) & 1u) << t;
    }
    int r = g_rank[b][i];
    g_excRd[b][r][lane] = excw;              // dense fallback
    g_incRd[b][r][lane] = incw;

    // padded sparse exc list (rank entries), staged in smem, vector-stored
    int c = __popc(excw);
    int v = c;
    #pragma unroll
    for (int o = 1; o < 32; o <<= 1) {
        int t = __shfl_up_sync(FULL, v, o);
        if (lane >= o) v += t;
    }
    int tot = __shfl_sync(FULL, v, 31);
    if (lane == 0) g_excCnt[b][r] = (tot <= ECAP) ? (unsigned short)tot : (unsigned short)0xFFFF;
    if (tot <= ECAP) {
        wst[wInB][lane] = 0xFFFF;
        if (lane < ECAP - 32) wst[wInB][32 + lane] = 0xFFFF;
        __syncwarp();
        int p = v - c;
        unsigned m = excw;
        while (m) {
            int t = __ffs(m) - 1;
            m &= m - 1;
            wst[wInB][p++] = (unsigned short)(lane * 32 + t);
        }
        __syncwarp();
        if (lane < ECAP / 4)                 // 11 uint2 = 88 bytes
            ((uint2*)&g_excList[b][r][0])[lane] = ((uint2*)&wst[wInB][0])[lane];
    }
}

// ---------------- K3: serial greedy selection, warp-scatter exc -------------
// dynamic smem layout:
//   [0)        unsigned sInc[N*W]              131072 B
//   [131072)   unsigned short sList[N*ECAP]     90112 B
//   [221184)   unsigned short sCnt[N]            2048 B   (total 223232)
#define SMEM_SEL_BYTES (131072 + 90112 + 2048)

__global__ void select_kernel(float* __restrict__ out_mask) {
    extern __shared__ char sm[];
    unsigned*       sInc  = (unsigned*)sm;
    unsigned short* sList = (unsigned short*)(sm + 131072);
    unsigned short* sCnt  = (unsigned short*)(sm + 221184);
    __shared__ unsigned stmp[2][W];

    int b = blockIdx.x;
    int tid = threadIdx.x;
    // cooperative staging from L2 (256 threads)
    {
        const uint4* src = (const uint4*)&g_incRd[b][0][0];
        uint4* dst = (uint4*)sInc;
        for (int i = tid; i < (N * W * 4) / 16; i += 256) dst[i] = src[i];
        const uint4* ls = (const uint4*)&g_excList[b][0][0];
        uint4* ld = (uint4*)sList;
        for (int i = tid; i < (N * ECAP * 2) / 16; i += 256) ld[i] = ls[i];
        const uint4* cs = (const uint4*)&g_excCnt[b][0];
        uint4* cd = (uint4*)sCnt;
        for (int i = tid; i < (N * 2) / 16; i += 256) cd[i] = cs[i];
        if (tid < W) { stmp[0][tid] = 0; stmp[1][tid] = 0; }
    }
    __syncthreads();
    if (tid >= 32) return;                    // warp 0 runs the serial loop
    int lane = tid;

    unsigned av = FULL;                       // node_mask all-true
    unsigned sel = 0;                         // rank-space selected set
    unsigned fr = (lane == 0) ? 1u : 0u;      // initial frontier = rank 0
    int r = 0;
    int par = 0;

    int guard = 0;
    while (guard++ < 2 * N) {
        if (lane == (r >> 5)) sel |= 1u << (r & 31);
        int cnt = sCnt[r];                    // broadcast LDS
        unsigned incw = sInc[(r << 5) + lane];
        unsigned* tb = stmp[par];
        if (cnt <= ECAP) {
            int base = r * ECAP;
            unsigned e0 = sList[base + lane];
            unsigned e1 = (lane < ECAP - 32) ? (unsigned)sList[base + 32 + lane] : 0xFFFFu;
            if (e0 < N) atomicOr(&tb[e0 >> 5], 1u << (e0 & 31));
            if (e1 < N) atomicOr(&tb[e1 >> 5], 1u << (e1 & 31));
            __syncwarp();
            unsigned ex = tb[lane];
            tb[lane] = 0;                     // clear for reuse 2 iters later
            av &= ~ex;                        // exc includes self bit
        } else {
            __syncwarp();
            av &= ~g_excRd[b][r][lane];       // rare dense fallback
        }
        par ^= 1;
        fr = (fr | incw) & av;
        unsigned bal = __ballot_sync(FULL, fr != 0u);
        if (!bal) {                           // frontier died -> restart on av
            fr = av;
            bal = __ballot_sync(FULL, av != 0u);
            if (!bal) break;
        }
        int lead = __ffs(bal) - 1;
        unsigned wrd = __shfl_sync(FULL, fr, lead);
        r = (lead << 5) + __ffs(wrd) - 1;     // min rank in frontier
    }

    // convert rank-space sel to node space (reuse stmp[0], all-zero now)
    unsigned m = sel;
    while (m) {
        int t = __ffs(m) - 1;
        m &= m - 1;
        int node = g_inv[b][lane * 32 + t];
        atomicOr(&stmp[0][node >> 5], 1u << (node & 31));
    }
    __syncwarp();
    unsigned selN = stmp[0][lane];

    // stable top_k permutation: selected ascending, then unselected ascending
    int cnt = __popc(selN);
    int v = cnt;
    #pragma unroll
    for (int o = 1; o < 32; o <<= 1) {
        int n2 = __shfl_up_sync(FULL, v, o);
        if (lane >= o) v += n2;
    }
    int K = __shfl_sync(FULL, v, 31);
    int selpos = v - cnt;
    int unspos = K + (lane * 32 - selpos);
    #pragma unroll
    for (int i = 0; i < 32; ++i) {
        int node = lane * 32 + i;
        if ((selN >> i) & 1u) g_perm[b][selpos++] = node;
        else                  g_perm[b][unspos++] = node;
    }
    if (lane == 0) g_K[b] = K;
    #pragma unroll
    for (int w = 0; w < W; ++w) {
        int j = w * 32 + lane;
        out_mask[b * N + j] = (j < K) ? 1.0f : 0.0f;
    }
}

// ---------------- K4: pooled features x_p and pos_p (live rows only) --------
__global__ void xp_kernel(const float* __restrict__ x, const float* __restrict__ pos,
                          float* __restrict__ out_x, float* __restrict__ out_pos) {
    int b = blockIdx.y, k = blockIdx.x;
    if (k >= g_K[b]) return;                   // padding already zero-filled
    int f = threadIdx.x;                       // 256 threads == F
    __shared__ int spk, snn;
    __shared__ int list[MAXL];
    if (f == 0) spk = g_perm[b][k];
    __syncthreads();
    if (f < 32) {
        unsigned wd = g_bits1[b][spk][f];
        int c = __popc(wd);
        int v = c;
        #pragma unroll
        for (int o = 1; o < 32; o <<= 1) {
            int t = __shfl_up_sync(FULL, v, o);
            if (f >= o) v += t;
        }
        int p = v - c;
        while (wd) {
            int bt = __ffs(wd) - 1;
            wd &= wd - 1;
            list[p++] = f * 32 + bt;
        }
        if (f == 31) snn = v;
    }
    __syncthreads();
    int nn = snn;

    float acc = 0.0f;
    #pragma unroll 4
    for (int i = 0; i < nn; ++i)
        acc += x[((size_t)b * N + list[i]) * F + f];
    out_x[((size_t)b * N + k) * F + f] = acc;

    if (f < 3) {
        float p = 0.0f;
        for (int i = 0; i < nn; ++i)
            p += pos[((size_t)b * N + list[i]) * 3 + f];
        out_pos[((size_t)b * N + k) * 3 + f] = p / (float)nn;
    }
}

// ---------------- K5: coarsened adjacency, one block per batch --------------
__global__ void a_kernel(float* __restrict__ out_a) {
    int b = blockIdx.x;
    int K = g_K[b];
    __shared__ unsigned srows[MAXK][33];
    __shared__ int sperm[MAXK];
    int KC = K < MAXK ? K : MAXK;
    for (int j = threadIdx.x; j < KC; j += blockDim.x) sperm[j] = g_perm[b][j];
    __syncthreads();
    for (int t = threadIdx.x; t < KC * W; t += blockDim.x) {
        int j = t >> 5, w = t & 31;
        srows[j][w] = g_bitsA[b][sperm[j]][w];
    }
    __syncthreads();
    for (int idx = threadIdx.x; idx < K * K; idx += blockDim.x) {
        int i = idx / K, j = idx - i * K;
        int pi = (i < KC) ? sperm[i] : g_perm[b][i];
        const unsigned* ri = (i < KC) ? &srows[i][0] : &g_bitsA[b][pi][0];
        const unsigned* rj;
        if (j < KC) rj = &srows[j][0];
        else        rj = &g_bitsA[b][g_perm[b][j]][0];
        int s = 0;
        #pragma unroll
        for (int w = 0; w < W; ++w) s += __popc(ri[w] & rj[w]);
        s += (rj[pi >> 5] >> (pi & 31)) & 1;   // diagonal self-term of (A+I)@A
        out_a[((size_t)b * N + i) * N + j] = (float)s;
    }
}

// ---------------- launch ----------------------------------------------------
extern "C" void kernel_launch(void* const* d_in, const int* in_sizes, int n_in,
                              void* d_out, int out_size) {
    const float *x = nullptr, *adj = nullptr, *pos = nullptr, *order = nullptr;
    for (int i = 0; i < n_in; ++i) {
        if      (in_sizes[i] == B * N * N) adj   = (const float*)d_in[i];
        else if (in_sizes[i] == B * N * F) x     = (const float*)d_in[i];
        else if (in_sizes[i] == B * N * 3) pos   = (const float*)d_in[i];
        else if (in_sizes[i] == B * N) { if (!order) order = (const float*)d_in[i]; }
    }
    float* out = (float*)d_out;

    cudaFuncSetAttribute(select_kernel,
                         cudaFuncAttributeMaxDynamicSharedMemorySize, SMEM_SEL_BYTES);

    pack_zero_kernel<<<TOTAL_BLKS, 256>>>(adj, out);
    rank_kernel     <<<B * 8, 128>>>(order);
    inc_perm_kernel <<<(B * N) / 8, 256>>>();
    select_kernel   <<<B, 256, SMEM_SEL_BYTES>>>(out + OFF_M);
    {
        dim3 g(N, B);
        xp_kernel<<<g, F>>>(x, pos, out + OFF_X, out + OFF_P);
    }
    a_kernel<<<B, 1024>>>(out + OFF_A);
}

// round 9
// speedup vs baseline: 1.2561x; 1.0013x over previous
#include <cuda_runtime.h>
#include <cstdint>

#define B 4
#define N 1024
#define F 256
#define W 32            // 32 x u32 words per 1024-bit row
#define FULL 0xFFFFFFFFu

#define PACK_BLKS 512   // 512 blocks * 8 warps = 4096 rows
#define ZERO_BLKS 1536
#define RANK_BLKS 16    // 16 blocks * 256 thr = 4096 rank slots
#define TOTAL_BLKS (PACK_BLKS + ZERO_BLKS + RANK_BLKS)
#define MAXK 344        // smem row-cache capacity in a_kernel (guarded fallback)
#define MAXL 128        // neighbor-list capacity in xp_kernel
#define ECAP 44         // sparse exc-list capacity per row (dense fallback if exceeded)
#define XPB 192         // xp blocks per batch

// ---------------- scratch (device globals; no allocations allowed) ----------
__device__ unsigned       g_bitsA  [B][N][W];    // adj rows (node space)
__device__ unsigned       g_bits1  [B][N][W];    // (adj+I) rows (node space)
__device__ unsigned       g_excRd  [B][N][W];    // dense exc rows, rank space (fallback)
__device__ unsigned       g_incRd  [B][N][W];    // dense inc rows, rank space
__device__ __align__(16) unsigned short g_excList[B][N][ECAP]; // sparse exc (rank entries, 0xFFFF pad)
__device__ __align__(16) unsigned short g_excCnt [B][N];       // count or 0xFFFF sentinel
__device__ int            g_rank   [B][N];
__device__ int            g_inv    [B][N];
__device__ int            g_perm   [B][N];
__device__ int            g_K      [B];

// Output layout (float32, concatenated):
#define OFF_X   0
#define OFF_P   (B*N*F)
#define OFF_A   (B*N*F + B*N*3)
#define OFF_M   (B*N*F + B*N*3 + B*N*N)
#define NZERO4  ((B*N*F + B*N*3 + B*N*N) / 4)

// ---------------- K0: pack bitmasks + zero-fill outputs + rank (fused) ------
__global__ void pack_zero_rank_kernel(const float* __restrict__ adj,
                                      const float* __restrict__ order,
                                      float* __restrict__ out) {
    if (blockIdx.x >= PACK_BLKS + ZERO_BLKS) {
        // ---- rank sub-kernel: stable sorted position of order[b][i] ----
        int zb = blockIdx.x - (PACK_BLKS + ZERO_BLKS);      // 0..15
        int b = zb >> 2;
        int i = (zb & 3) * 256 + threadIdx.x;
        __shared__ float so[N];
        for (int j = threadIdx.x; j < N; j += 256) so[j] = order[b * N + j];
        __syncthreads();
        float oi = so[i];
        int r = 0;
        const float4* s4 = (const float4*)so;
        #pragma unroll 8
        for (int j4 = 0; j4 < N / 4; ++j4) {
            float4 v = s4[j4];
            int j = j4 * 4;
            r += (v.x < oi) || (v.x == oi && (j + 0) < i);
            r += (v.y < oi) || (v.y == oi && (j + 1) < i);
            r += (v.z < oi) || (v.z == oi && (j + 2) < i);
            r += (v.w < oi) || (v.w == oi && (j + 3) < i);
        }
        g_rank[b][i] = r;
        g_inv[b][r] = i;
        return;
    }
    if (blockIdx.x >= PACK_BLKS) {
        // ---- zero-fill x_p, pos_p, a regions ----
        int zb = blockIdx.x - PACK_BLKS;
        float4 z = make_float4(0.f, 0.f, 0.f, 0.f);
        float4* o = (float4*)out;
        for (int i = zb * blockDim.x + threadIdx.x; i < NZERO4; i += ZERO_BLKS * blockDim.x)
            o[i] = z;
        return;
    }
    // ---- pack adj rows ----
    int warp = (blockIdx.x * blockDim.x + threadIdx.x) >> 5;   // 0..4095
    int lane = threadIdx.x & 31;
    int b = warp >> 10, i = warp & (N - 1);
    const float4* r4 = (const float4*)(adj + ((size_t)b * N + i) * N) + lane * 8;
    unsigned w = 0;
    #pragma unroll
    for (int j = 0; j < 8; ++j) {
        float4 v = r4[j];
        w |= (v.x != 0.f ? 1u : 0u) << (4 * j)
           | (v.y != 0.f ? 1u : 0u) << (4 * j + 1)
           | (v.z != 0.f ? 1u : 0u) << (4 * j + 2)
           | (v.w != 0.f ? 1u : 0u) << (4 * j + 3);
    }
    g_bitsA[b][i][lane] = w;
    unsigned m1 = w | ((lane == (i >> 5)) ? (1u << (i & 31)) : 0u);
    g_bits1[b][i][lane] = m1;
}

// ---------------- K1: inc rows + permute to RANK space + padded sparse exc --
__global__ void inc_perm_kernel() {
    int warp = (blockIdx.x * blockDim.x + threadIdx.x) >> 5;
    int wInB = (threadIdx.x >> 5);           // 0..7
    int lane = threadIdx.x & 31;
    int b = warp >> 10, i = warp & (N - 1);
    __shared__ unsigned short wst[8][ECAP];

    unsigned exc = g_bits1[b][i][lane];
    unsigned acc = 0;
    #pragma unroll 4
    for (int w = 0; w < W; ++w) {
        unsigned word = __shfl_sync(FULL, exc, w);
        while (word) {
            int bit = __ffs(word) - 1;
            word &= word - 1;
            acc |= g_bitsA[b][w * 32 + bit][lane];
        }
    }
    // column permutation to rank space
    int sj[32];
    const int4* inv4 = (const int4*)&g_inv[b][0];
    #pragma unroll
    for (int q = 0; q < 8; ++q) {
        int4 v = inv4[lane * 8 + q];
        sj[4 * q] = v.x; sj[4 * q + 1] = v.y; sj[4 * q + 2] = v.z; sj[4 * q + 3] = v.w;
    }
    unsigned excw = 0, incw = 0;
    #pragma unroll
    for (int t = 0; t < 32; ++t) {
        int j = sj[t];
        unsigned ew = __shfl_sync(FULL, exc, j >> 5);
        unsigned iw = __shfl_sync(FULL, acc, j >> 5);
        excw |= ((ew >> (j & 31)) & 1u) << t;
        incw |= ((iw >> (j & 31)) & 1u) << t;
    }
    int r = g_rank[b][i];
    g_excRd[b][r][lane] = excw;              // dense fallback
    g_incRd[b][r][lane] = incw;

    // padded sparse exc list (rank entries), staged in smem, vector-stored.
    // ALWAYS written (overflow rows get all-0xFFFF so scatter is a no-op).
    int c = __popc(excw);
    int v = c;
    #pragma unroll
    for (int o = 1; o < 32; o <<= 1) {
        int t = __shfl_up_sync(FULL, v, o);
        if (lane >= o) v += t;
    }
    int tot = __shfl_sync(FULL, v, 31);
    if (lane == 0) g_excCnt[b][r] = (tot <= ECAP) ? (unsigned short)tot : (unsigned short)0xFFFF;
    wst[wInB][lane] = 0xFFFF;
    if (lane < ECAP - 32) wst[wInB][32 + lane] = 0xFFFF;
    __syncwarp();
    if (tot <= ECAP) {
        int p = v - c;
        unsigned m = excw;
        while (m) {
            int t = __ffs(m) - 1;
            m &= m - 1;
            wst[wInB][p++] = (unsigned short)(lane * 32 + t);
        }
    }
    __syncwarp();
    if (lane < ECAP / 4)                 // 11 uint2 = 88 bytes
        ((uint2*)&g_excList[b][r][0])[lane] = ((uint2*)&wst[wInB][0])[lane];
}

// ---------------- K2: serial greedy selection, warp-scatter exc -------------
// dynamic smem layout:
//   [0)        unsigned sInc[N*W]              131072 B
//   [131072)   unsigned short sList[N*ECAP]     90112 B
//   [221184)   unsigned short sCnt[N]            2048 B   (total 223232)
#define SMEM_SEL_BYTES (131072 + 90112 + 2048)

__global__ void select_kernel(float* __restrict__ out_mask) {
    extern __shared__ char sm[];
    unsigned*       sInc  = (unsigned*)sm;
    unsigned short* sList = (unsigned short*)(sm + 131072);
    unsigned short* sCnt  = (unsigned short*)(sm + 221184);
    __shared__ unsigned stmp[2][W];

    int b = blockIdx.x;
    int tid = threadIdx.x;
    // cooperative staging from L2 (256 threads)
    {
        const uint4* src = (const uint4*)&g_incRd[b][0][0];
        uint4* dst = (uint4*)sInc;
        for (int i = tid; i < (N * W * 4) / 16; i += 256) dst[i] = src[i];
        const uint4* ls = (const uint4*)&g_excList[b][0][0];
        uint4* ld = (uint4*)sList;
        for (int i = tid; i < (N * ECAP * 2) / 16; i += 256) ld[i] = ls[i];
        const uint4* cs = (const uint4*)&g_excCnt[b][0];
        uint4* cd = (uint4*)sCnt;
        for (int i = tid; i < (N * 2) / 16; i += 256) cd[i] = cs[i];
        if (tid < W) { stmp[0][tid] = 0; stmp[1][tid] = 0; }
    }
    __syncthreads();
    if (tid >= 32) return;                    // warp 0 runs the serial loop
    int lane = tid;

    unsigned av = FULL;                       // node_mask all-true
    unsigned sel = 0;                         // rank-space selected set
    unsigned fr = (lane == 0) ? 1u : 0u;      // initial frontier = rank 0
    int r = 0;
    int par = 0;

    int guard = 0;
    while (guard++ < 2 * N) {
        if (lane == (r >> 5)) sel |= 1u << (r & 31);
        unsigned incw = sInc[(r << 5) + lane];          // independent LDS, early
        unsigned cnt  = sCnt[r];                        // broadcast LDS, early
        unsigned* tb = stmp[par];
        if (lane < ECAP / 2) {                          // 22 lanes scatter 2 entries each
            unsigned pr = ((const unsigned*)(sList + r * ECAP))[lane];
            unsigned e0 = pr & 0xFFFFu, e1 = pr >> 16;
            if (e0 < N) atomicOr(&tb[e0 >> 5], 1u << (e0 & 31));
            if (e1 < N) atomicOr(&tb[e1 >> 5], 1u << (e1 & 31));
        }
        __syncwarp();
        unsigned ex = tb[lane];
        tb[lane] = 0;                                   // clear for reuse 2 iters later
        if (cnt > ECAP) ex |= g_excRd[b][r][lane];      // rare dense fallback (additive)
        av &= ~ex;                                      // exc includes self bit
        fr = (fr | incw) & av;
        int val = fr ? ((lane << 5) + __ffs(fr) - 1) : N;
        val = __reduce_min_sync(FULL, val);             // min rank in frontier
        if (val >= N) {                                 // frontier died -> restart on av
            fr = av;
            val = fr ? ((lane << 5) + __ffs(fr) - 1) : N;
            val = __reduce_min_sync(FULL, val);
            if (val >= N) break;                        // av empty -> done
        }
        r = val;
        par ^= 1;
    }

    // convert rank-space sel to node space (reuse stmp[0], all-zero now)
    unsigned m = sel;
    while (m) {
        int t = __ffs(m) - 1;
        m &= m - 1;
        int node = g_inv[b][lane * 32 + t];
        atomicOr(&stmp[0][node >> 5], 1u << (node & 31));
    }
    __syncwarp();
    unsigned selN = stmp[0][lane];

    // stable top_k permutation: selected ascending, then unselected ascending
    int cnt = __popc(selN);
    int v = cnt;
    #pragma unroll
    for (int o = 1; o < 32; o <<= 1) {
        int n2 = __shfl_up_sync(FULL, v, o);
        if (lane >= o) v += n2;
    }
    int K = __shfl_sync(FULL, v, 31);
    int selpos = v - cnt;
    int unspos = K + (lane * 32 - selpos);
    #pragma unroll
    for (int i = 0; i < 32; ++i) {
        int node = lane * 32 + i;
        if ((selN >> i) & 1u) g_perm[b][selpos++] = node;
        else                  g_perm[b][unspos++] = node;
    }
    if (lane == 0) g_K[b] = K;
    #pragma unroll
    for (int w = 0; w < W; ++w) {
        int j = w * 32 + lane;
        out_mask[b * N + j] = (j < K) ? 1.0f : 0.0f;
    }
}

// ---------------- K3: pooled features x_p and pos_p (live rows only) --------
__global__ void xp_kernel(const float* __restrict__ x, const float* __restrict__ pos,
                          float* __restrict__ out_x, float* __restrict__ out_pos) {
    int b = blockIdx.y;
    int K = g_K[b];
    int f = threadIdx.x;                       // 256 threads == F
    __shared__ int spk, snn;
    __shared__ int list[MAXL];
    for (int k = blockIdx.x; k < K; k += XPB) {
        if (f == 0) spk = g_perm[b][k];
        __syncthreads();
        if (f < 32) {
            unsigned wd = g_bits1[b][spk][f];
            int c = __popc(wd);
            int v = c;
            #pragma unroll
            for (int o = 1; o < 32; o <<= 1) {
                int t = __shfl_up_sync(FULL, v, o);
                if (f >= o) v += t;
            }
            int p = v - c;
            while (wd) {
                int bt = __ffs(wd) - 1;
                wd &= wd - 1;
                list[p++] = f * 32 + bt;
            }
            if (f == 31) snn = v;
        }
        __syncthreads();
        int nn = snn;

        float acc = 0.0f;
        #pragma unroll 4
        for (int i = 0; i < nn; ++i)
            acc += x[((size_t)b * N + list[i]) * F + f];
        out_x[((size_t)b * N + k) * F + f] = acc;

        if (f < 3) {
            float p = 0.0f;
            for (int i = 0; i < nn; ++i)
                p += pos[((size_t)b * N + list[i]) * 3 + f];
            out_pos[((size_t)b * N + k) * 3 + f] = p / (float)nn;
        }
        __syncthreads();
    }
}

// ---------------- K4: coarsened adjacency, one block per batch --------------
__global__ void a_kernel(float* __restrict__ out_a) {
    int b = blockIdx.x;
    int K = g_K[b];
    __shared__ unsigned srows[MAXK][33];
    __shared__ int sperm[MAXK];
    int KC = K < MAXK ? K : MAXK;
    for (int j = threadIdx.x; j < KC; j += blockDim.x) sperm[j] = g_perm[b][j];
    __syncthreads();
    for (int t = threadIdx.x; t < KC * W; t += blockDim.x) {
        int j = t >> 5, w = t & 31;
        srows[j][w] = g_bitsA[b][sperm[j]][w];
    }
    __syncthreads();
    for (int idx = threadIdx.x; idx < K * K; idx += blockDim.x) {
        int i = idx / K, j = idx - i * K;
        int pi = (i < KC) ? sperm[i] : g_perm[b][i];
        const unsigned* ri = (i < KC) ? &srows[i][0] : &g_bitsA[b][pi][0];
        const unsigned* rj;
        if (j < KC) rj = &srows[j][0];
        else        rj = &g_bitsA[b][g_perm[b][j]][0];
        int s = 0;
        #pragma unroll
        for (int w = 0; w < W; ++w) s += __popc(ri[w] & rj[w]);
        s += (rj[pi >> 5] >> (pi & 31)) & 1;   // diagonal self-term of (A+I)@A
        out_a[((size_t)b * N + i) * N + j] = (float)s;
    }
}

// ---------------- launch ----------------------------------------------------
extern "C" void kernel_launch(void* const* d_in, const int* in_sizes, int n_in,
                              void* d_out, int out_size) {
    const float *x = nullptr, *adj = nullptr, *pos = nullptr, *order = nullptr;
    for (int i = 0; i < n_in; ++i) {
        if      (in_sizes[i] == B * N * N) adj   = (const float*)d_in[i];
        else if (in_sizes[i] == B * N * F) x     = (const float*)d_in[i];
        else if (in_sizes[i] == B * N * 3) pos   = (const float*)d_in[i];
        else if (in_sizes[i] == B * N) { if (!order) order = (const float*)d_in[i]; }
    }
    float* out = (float*)d_out;

    cudaFuncSetAttribute(select_kernel,
                         cudaFuncAttributeMaxDynamicSharedMemorySize, SMEM_SEL_BYTES);

    pack_zero_rank_kernel<<<TOTAL_BLKS, 256>>>(adj, order, out);
    inc_perm_kernel      <<<(B * N) / 8, 256>>>();
    select_kernel        <<<B, 256, SMEM_SEL_BYTES>>>(out + OFF_M);
    {
        dim3 g(XPB, B);
        xp_kernel<<<g, F>>>(x, pos, out + OFF_X, out + OFF_P);
    }
    a_kernel<<<B, 1024>>>(out + OFF_A);
}

// round 10
// speedup vs baseline: 1.4061x; 1.1194x over previous
#include <cuda_runtime.h>
#include <cstdint>

#define B 4
#define N 1024
#define F 256
#define W 32            // 32 x u32 words per 1024-bit row
#define FULL 0xFFFFFFFFu

#define PACK_BLKS 512   // 512 blocks * 8 warps = 4096 rows
#define ZERO_BLKS 1536
#define RANK_BLKS 16    // 16 blocks * 256 thr = 4096 rank slots
#define TOTAL_BLKS (PACK_BLKS + ZERO_BLKS + RANK_BLKS)
#define MAXK 344        // smem row-cache capacity in a_kernel (guarded fallback)
#define MAXL 128        // neighbor-list capacity in xp_kernel
#define XPB 192         // xp blocks per batch
#define RCAP 864        // ranks with SMEM-resident {exc,inc} rows in select

// ---------------- scratch (device globals; no allocations allowed) ----------
__device__ unsigned g_bitsA  [B][N][W];  // adj rows (node space)
__device__ unsigned g_bits1  [B][N][W];  // (adj+I) rows (node space)
__device__ uint2    g_excincR[B][N][W];  // rank-space rows: {exc word, inc word}
__device__ int      g_rank   [B][N];
__device__ int      g_inv    [B][N];
__device__ int      g_perm   [B][N];
__device__ int      g_K      [B];

// Output layout (float32, concatenated):
#define OFF_X   0
#define OFF_P   (B*N*F)
#define OFF_A   (B*N*F + B*N*3)
#define OFF_M   (B*N*F + B*N*3 + B*N*N)
#define NZERO4  ((B*N*F + B*N*3 + B*N*N) / 4)

// ---------------- K0: pack bitmasks + zero-fill outputs + rank (fused) ------
__global__ void pack_zero_rank_kernel(const float* __restrict__ adj,
                                      const float* __restrict__ order,
                                      float* __restrict__ out) {
    if (blockIdx.x >= PACK_BLKS + ZERO_BLKS) {
        // ---- rank sub-kernel: stable sorted position of order[b][i] ----
        int zb = blockIdx.x - (PACK_BLKS + ZERO_BLKS);      // 0..15
        int b = zb >> 2;
        int i = (zb & 3) * 256 + threadIdx.x;
        __shared__ float so[N];
        for (int j = threadIdx.x; j < N; j += 256) so[j] = order[b * N + j];
        __syncthreads();
        float oi = so[i];
        int r = 0;
        const float4* s4 = (const float4*)so;
        #pragma unroll 8
        for (int j4 = 0; j4 < N / 4; ++j4) {
            float4 v = s4[j4];
            int j = j4 * 4;
            r += (v.x < oi) || (v.x == oi && (j + 0) < i);
            r += (v.y < oi) || (v.y == oi && (j + 1) < i);
            r += (v.z < oi) || (v.z == oi && (j + 2) < i);
            r += (v.w < oi) || (v.w == oi && (j + 3) < i);
        }
        g_rank[b][i] = r;
        g_inv[b][r] = i;
        return;
    }
    if (blockIdx.x >= PACK_BLKS) {
        // ---- zero-fill x_p, pos_p, a regions ----
        int zb = blockIdx.x - PACK_BLKS;
        float4 z = make_float4(0.f, 0.f, 0.f, 0.f);
        float4* o = (float4*)out;
        for (int i = zb * blockDim.x + threadIdx.x; i < NZERO4; i += ZERO_BLKS * blockDim.x)
            o[i] = z;
        return;
    }
    // ---- pack adj rows ----
    int warp = (blockIdx.x * blockDim.x + threadIdx.x) >> 5;   // 0..4095
    int lane = threadIdx.x & 31;
    int b = warp >> 10, i = warp & (N - 1);
    const float4* r4 = (const float4*)(adj + ((size_t)b * N + i) * N) + lane * 8;
    unsigned w = 0;
    #pragma unroll
    for (int j = 0; j < 8; ++j) {
        float4 v = r4[j];
        w |= (v.x != 0.f ? 1u : 0u) << (4 * j)
           | (v.y != 0.f ? 1u : 0u) << (4 * j + 1)
           | (v.z != 0.f ? 1u : 0u) << (4 * j + 2)
           | (v.w != 0.f ? 1u : 0u) << (4 * j + 3);
    }
    g_bitsA[b][i][lane] = w;
    unsigned m1 = w | ((lane == (i >> 5)) ? (1u << (i & 31)) : 0u);
    g_bits1[b][i][lane] = m1;
}

// ---------------- K1: inc rows + permute {exc,inc} into RANK space ----------
__global__ void inc_perm_kernel() {
    int warp = (blockIdx.x * blockDim.x + threadIdx.x) >> 5;
    int lane = threadIdx.x & 31;
    int b = warp >> 10, i = warp & (N - 1);

    unsigned exc = g_bits1[b][i][lane];
    unsigned acc = 0;
    #pragma unroll 4
    for (int w = 0; w < W; ++w) {
        unsigned word = __shfl_sync(FULL, exc, w);
        while (word) {
            int bit = __ffs(word) - 1;
            word &= word - 1;
            acc |= g_bitsA[b][w * 32 + bit][lane];
        }
    }
    // column permutation to rank space
    int sj[32];
    const int4* inv4 = (const int4*)&g_inv[b][0];
    #pragma unroll
    for (int q = 0; q < 8; ++q) {
        int4 v = inv4[lane * 8 + q];
        sj[4 * q] = v.x; sj[4 * q + 1] = v.y; sj[4 * q + 2] = v.z; sj[4 * q + 3] = v.w;
    }
    unsigned excw = 0, incw = 0;
    #pragma unroll
    for (int t = 0; t < 32; ++t) {
        int j = sj[t];
        unsigned ew = __shfl_sync(FULL, exc, j >> 5);
        unsigned iw = __shfl_sync(FULL, acc, j >> 5);
        excw |= ((ew >> (j & 31)) & 1u) << t;
        incw |= ((iw >> (j & 31)) & 1u) << t;
    }
    int r = g_rank[b][i];
    g_excincR[b][r][lane] = make_uint2(excw, incw);
}

// ---------------- K2: serial greedy selection, dense uint2 SMEM rows --------
// dynamic smem: uint2 sEI[RCAP*W] = 864*32*8 = 221184 B
#define SMEM_SEL_BYTES (RCAP * W * 8)

__global__ void select_kernel(float* __restrict__ out_mask) {
    extern __shared__ char sm[];
    uint2* sEI = (uint2*)sm;
    __shared__ unsigned snode[W];

    int b = blockIdx.x;
    int tid = threadIdx.x;
    // cooperative staging from L2 (256 threads): rows for ranks < RCAP
    {
        const uint4* src = (const uint4*)&g_excincR[b][0][0];
        uint4* dst = (uint4*)sEI;
        for (int i = tid; i < SMEM_SEL_BYTES / 16; i += 256) dst[i] = src[i];
        if (tid < W) snode[tid] = 0;
    }
    __syncthreads();
    if (tid >= 32) return;                    // warp 0 runs the serial loop
    int lane = tid;

    unsigned av = FULL;                       // node_mask all-true
    unsigned sel = 0;                         // rank-space selected set
    unsigned fr = (lane == 0) ? 1u : 0u;      // initial frontier = rank 0
    int r = 0;

    int guard = 0;
    while (guard++ < 2 * N) {
        if (lane == (r >> 5)) sel |= 1u << (r & 31);
        uint2 ei = (r < RCAP) ? sEI[(r << 5) + lane]    // one LDS.64
                              : g_excincR[b][r][lane];  // rare high-rank fallback
        av &= ~ei.x;                          // exc includes self bit
        fr = (fr | ei.y) & av;
        int val = fr ? ((lane << 5) + __ffs(fr) - 1) : N;
        val = __reduce_min_sync(FULL, val);   // min rank in frontier
        if (val >= N) {                       // frontier died -> restart on av
            fr = av;
            val = fr ? ((lane << 5) + __ffs(fr) - 1) : N;
            val = __reduce_min_sync(FULL, val);
            if (val >= N) break;              // av empty -> done
        }
        r = val;
    }

    // convert rank-space sel to node space
    unsigned m = sel;
    while (m) {
        int t = __ffs(m) - 1;
        m &= m - 1;
        int node = g_inv[b][lane * 32 + t];
        atomicOr(&snode[node >> 5], 1u << (node & 31));
    }
    __syncwarp();
    unsigned selN = snode[lane];

    // stable top_k permutation: selected ascending, then unselected ascending
    int cnt = __popc(selN);
    int v = cnt;
    #pragma unroll
    for (int o = 1; o < 32; o <<= 1) {
        int n2 = __shfl_up_sync(FULL, v, o);
        if (lane >= o) v += n2;
    }
    int K = __shfl_sync(FULL, v, 31);
    int selpos = v - cnt;
    int unspos = K + (lane * 32 - selpos);
    #pragma unroll
    for (int i = 0; i < 32; ++i) {
        int node = lane * 32 + i;
        if ((selN >> i) & 1u) g_perm[b][selpos++] = node;
        else                  g_perm[b][unspos++] = node;
    }
    if (lane == 0) g_K[b] = K;
    #pragma unroll
    for (int w = 0; w < W; ++w) {
        int j = w * 32 + lane;
        out_mask[b * N + j] = (j < K) ? 1.0f : 0.0f;
    }
}

// ---------------- K3: pooled features x_p and pos_p (live rows only) --------
__global__ void xp_kernel(const float* __restrict__ x, const float* __restrict__ pos,
                          float* __restrict__ out_x, float* __restrict__ out_pos) {
    int b = blockIdx.y;
    int K = g_K[b];
    int f = threadIdx.x;                       // 256 threads == F
    __shared__ int spk, snn;
    __shared__ int list[MAXL];
    for (int k = blockIdx.x; k < K; k += XPB) {
        if (f == 0) spk = g_perm[b][k];
        __syncthreads();
        if (f < 32) {
            unsigned wd = g_bits1[b][spk][f];
            int c = __popc(wd);
            int v = c;
            #pragma unroll
            for (int o = 1; o < 32; o <<= 1) {
                int t = __shfl_up_sync(FULL, v, o);
                if (f >= o) v += t;
            }
            int p = v - c;
            while (wd) {
                int bt = __ffs(wd) - 1;
                wd &= wd - 1;
                list[p++] = f * 32 + bt;
            }
            if (f == 31) snn = v;
        }
        __syncthreads();
        int nn = snn;

        float acc = 0.0f;
        #pragma unroll 8
        for (int i = 0; i < nn; ++i)
            acc += __ldg(&x[((size_t)b * N + list[i]) * F + f]);
        out_x[((size_t)b * N + k) * F + f] = acc;

        if (f < 3) {
            float p = 0.0f;
            for (int i = 0; i < nn; ++i)
                p += __ldg(&pos[((size_t)b * N + list[i]) * 3 + f]);
            out_pos[((size_t)b * N + k) * 3 + f] = p / (float)nn;
        }
        __syncthreads();
    }
}

// ---------------- K4: coarsened adjacency, one block per batch --------------
__global__ void a_kernel(float* __restrict__ out_a) {
    int b = blockIdx.x;
    int K = g_K[b];
    __shared__ unsigned srows[MAXK][33];
    __shared__ int sperm[MAXK];
    int KC = K < MAXK ? K : MAXK;
    for (int j = threadIdx.x; j < KC; j += blockDim.x) sperm[j] = g_perm[b][j];
    __syncthreads();
    for (int t = threadIdx.x; t < KC * W; t += blockDim.x) {
        int j = t >> 5, w = t & 31;
        srows[j][w] = g_bitsA[b][sperm[j]][w];
    }
    __syncthreads();
    for (int idx = threadIdx.x; idx < K * K; idx += blockDim.x) {
        int i = idx / K, j = idx - i * K;
        int pi = (i < KC) ? sperm[i] : g_perm[b][i];
        const unsigned* ri = (i < KC) ? &srows[i][0] : &g_bitsA[b][pi][0];
        const unsigned* rj;
        if (j < KC) rj = &srows[j][0];
        else        rj = &g_bitsA[b][g_perm[b][j]][0];
        int s = 0;
        #pragma unroll
        for (int w = 0; w < W; ++w) s += __popc(ri[w] & rj[w]);
        s += (rj[pi >> 5] >> (pi & 31)) & 1;   // diagonal self-term of (A+I)@A
        out_a[((size_t)b * N + i) * N + j] = (float)s;
    }
}

// ---------------- launch ----------------------------------------------------
extern "C" void kernel_launch(void* const* d_in, const int* in_sizes, int n_in,
                              void* d_out, int out_size) {
    const float *x = nullptr, *adj = nullptr, *pos = nullptr, *order = nullptr;
    for (int i = 0; i < n_in; ++i) {
        if      (in_sizes[i] == B * N * N) adj   = (const float*)d_in[i];
        else if (in_sizes[i] == B * N * F) x     = (const float*)d_in[i];
        else if (in_sizes[i] == B * N * 3) pos   = (const float*)d_in[i];
        else if (in_sizes[i] == B * N) { if (!order) order = (const float*)d_in[i]; }
    }
    float* out = (float*)d_out;

    cudaFuncSetAttribute(select_kernel,
                         cudaFuncAttributeMaxDynamicSharedMemorySize, SMEM_SEL_BYTES);

    pack_zero_rank_kernel<<<TOTAL_BLKS, 256>>>(adj, order, out);
    inc_perm_kernel      <<<(B * N) / 8, 256>>>();
    select_kernel        <<<B, 256, SMEM_SEL_BYTES>>>(out + OFF_M);
    {
        dim3 g(XPB, B);
        xp_kernel<<<g, F>>>(x, pos, out + OFF_X, out + OFF_P);
    }
    a_kernel<<<B, 1024>>>(out + OFF_A);
}